// round 1
// baseline (speedup 1.0000x reference)
#include <cuda_runtime.h>
#include <math.h>

#define B      256
#define NNEG   1000
#define H      3
#define D      128
#define NMIN   250        // min(NUM_CLUSTER): neg ids are in [0, NMIN) by construction
#define EPSF   1e-6f

// -------- scratch (device globals; no allocations allowed) --------
__device__ float g_se_norm[B * H * D];       // normalized query embeddings
__device__ float g_sims[B * H * NMIN];       // half-sims (dot+1)*0.5 for c < NMIN
__device__ float g_posloss[B];
__device__ int   g_poslab[B * H];
__device__ float g_partial[B];

__device__ __forceinline__ float warp_sum(float v) {
#pragma unroll
    for (int o = 16; o > 0; o >>= 1) v += __shfl_xor_sync(0xffffffffu, v, o);
    return v;
}

// ---------------------------------------------------------------------------
// Kernel 1: normalize se rows, positive-path loss, stash positive labels.
// grid = B blocks, 96 threads (3 warps; warp w handles hierarchy h = w).
// ---------------------------------------------------------------------------
__global__ void k_norm_pos(const float* __restrict__ se,
                           const float* __restrict__ c0,
                           const float* __restrict__ c1,
                           const float* __restrict__ c2,
                           const int* __restrict__ i2c0,
                           const int* __restrict__ i2c1,
                           const int* __restrict__ i2c2,
                           const int* __restrict__ idx)
{
    int b    = blockIdx.x;
    int h    = threadIdx.x >> 5;     // 0..2
    int lane = threadIdx.x & 31;
    __shared__ float s_psim[H];

    // --- normalize se[b, h, :] (float4 per lane) ---
    float4 v = ((const float4*)(se + b * (H * D) + h * D))[lane];
    float ss = v.x * v.x + v.y * v.y + v.z * v.z + v.w * v.w;
    ss = warp_sum(ss);
    float inv = 1.0f / fmaxf(sqrtf(ss), 1e-12f);
    v.x *= inv; v.y *= inv; v.z *= inv; v.w *= inv;
    ((float4*)(g_se_norm + b * (H * D) + h * D))[lane] = v;

    // --- positive path ---
    const float* cents = (h == 0) ? c0 : ((h == 1) ? c1 : c2);
    const int*   i2c   = (h == 0) ? i2c0 : ((h == 1) ? i2c1 : i2c2);
    int cid = i2c[idx[b]];
    if (lane == 0) g_poslab[b * H + h] = cid;

    float4 cv = ((const float4*)(cents + (long)cid * D))[lane];
    float dot = v.x * cv.x + v.y * cv.y + v.z * cv.z + v.w * cv.w;
    float cs  = cv.x * cv.x + cv.y * cv.y + cv.z * cv.z + cv.w * cv.w;
    dot = warp_sum(dot);
    cs  = warp_sum(cs);
    if (lane == 0)
        s_psim[h] = (dot / fmaxf(sqrtf(cs), 1e-12f) + 1.0f) * 0.5f;
    __syncthreads();
    if (threadIdx.x == 0) {
        float p = s_psim[0] * s_psim[1] * s_psim[2];
        g_posloss[b] = -logf(p + EPSF);
    }
}

// ---------------------------------------------------------------------------
// Kernel 2: half-sim table for the hot centroid range c < NMIN.
// grid = (H, B/BT) blocks, 256 threads. BT se-rows live in smem; each warp
// streams one centroid row and produces BT dots + its sumsq (9 reductions).
// ---------------------------------------------------------------------------
#define BT 8
__global__ void k_sims(const float* __restrict__ c0,
                       const float* __restrict__ c1,
                       const float* __restrict__ c2)
{
    int h  = blockIdx.x;                 // 0..2
    int b0 = blockIdx.y * BT;            // base sample
    const float* cents = (h == 0) ? c0 : ((h == 1) ? c1 : c2);

    __shared__ float4 s_se[BT * 32];     // BT rows x 128 floats
    {
        int j = threadIdx.x >> 5;        // 0..7
        int l = threadIdx.x & 31;
        s_se[j * 32 + l] =
            ((const float4*)(g_se_norm + (b0 + j) * (H * D) + h * D))[l];
    }
    __syncthreads();

    int w = threadIdx.x >> 5, lane = threadIdx.x & 31;
    for (int c = w; c < NMIN; c += 8) {
        float4 cv = __ldg((const float4*)(cents + c * D) + lane);
        float cs = cv.x * cv.x + cv.y * cv.y + cv.z * cv.z + cv.w * cv.w;
        float dot[BT];
#pragma unroll
        for (int j = 0; j < BT; j++) {
            float4 s = s_se[j * 32 + lane];
            dot[j] = s.x * cv.x + s.y * cv.y + s.z * cv.z + s.w * cv.w;
        }
        cs = warp_sum(cs);
#pragma unroll
        for (int j = 0; j < BT; j++) dot[j] = warp_sum(dot[j]);
        if (lane == 0) {
            float inv = 1.0f / fmaxf(sqrtf(cs), 1e-12f);
#pragma unroll
            for (int j = 0; j < BT; j++)
                g_sims[(b0 + j) * (H * NMIN) + h * NMIN + c] =
                    (dot[j] * inv + 1.0f) * 0.5f;
        }
    }
}

// ---------------------------------------------------------------------------
// Rare fallback (never taken with this data distribution): direct dot for
// a negative cluster id outside the precomputed table range.
// ---------------------------------------------------------------------------
__device__ __noinline__ float halfsim_fallback(int b, int h, int id,
                                               const float* __restrict__ cents)
{
    const float* cv = cents + (long)id * D;
    const float* sv = g_se_norm + b * (H * D) + h * D;
    float dot = 0.f, cs = 0.f;
    for (int k = 0; k < D; k++) {
        float c = cv[k];
        dot += c * sv[k];
        cs  += c * c;
    }
    return (dot / fmaxf(sqrtf(cs), 1e-12f) + 1.0f) * 0.5f;
}

// ---------------------------------------------------------------------------
// Kernel 3: negative losses via table lookup + true-negative mask, per-b
// reduction, combine with positive loss.
// grid = B blocks, 256 threads.
// ---------------------------------------------------------------------------
__global__ void k_negloss(const int* __restrict__ negid,
                          const float* __restrict__ c0,
                          const float* __restrict__ c1,
                          const float* __restrict__ c2)
{
    int b   = blockIdx.x;
    int tid = threadIdx.x;
    __shared__ int   s_pl[H];
    __shared__ float s_sum[256];
    __shared__ float s_cnt[256];
    if (tid < H) s_pl[tid] = g_poslab[b * H + tid];
    __syncthreads();

    const float* simrow = g_sims + b * (H * NMIN);
    float sum = 0.f, cnt = 0.f;
    for (int n = tid; n < NNEG; n += 256) {
        int base = (b * NNEG + n) * H;
        int id0 = negid[base + 0];
        int id1 = negid[base + 1];
        int id2 = negid[base + 2];
        float p0 = (id0 < NMIN) ? simrow[0 * NMIN + id0]
                                : halfsim_fallback(b, 0, id0, c0);
        float p1 = (id1 < NMIN) ? simrow[1 * NMIN + id1]
                                : halfsim_fallback(b, 1, id1, c1);
        float p2 = (id2 < NMIN) ? simrow[2 * NMIN + id2]
                                : halfsim_fallback(b, 2, id2, c2);
        float p  = p0 * p1 * p2;
        bool tn = (id0 != s_pl[0]) | (id1 != s_pl[1]) | (id2 != s_pl[2]);
        if (tn) {
            sum += -logf(1.0f - p + EPSF);
            cnt += 1.0f;
        }
    }
    s_sum[tid] = sum;
    s_cnt[tid] = cnt;
    __syncthreads();
    for (int s = 128; s > 0; s >>= 1) {
        if (tid < s) {
            s_sum[tid] += s_sum[tid + s];
            s_cnt[tid] += s_cnt[tid + s];
        }
        __syncthreads();
    }
    if (tid == 0)
        g_partial[b] = g_posloss[b] + s_sum[0] / (s_cnt[0] + EPSF);
}

// ---------------------------------------------------------------------------
// Kernel 4: final mean over 2*B loss terms.
// ---------------------------------------------------------------------------
__global__ void k_final(float* __restrict__ out)
{
    int tid = threadIdx.x;
    __shared__ float s[256];
    s[tid] = g_partial[tid];
    __syncthreads();
    for (int st = 128; st > 0; st >>= 1) {
        if (tid < st) s[tid] += s[tid + st];
        __syncthreads();
    }
    if (tid == 0) out[0] = s[0] / (2.0f * (float)B);
}

// ---------------------------------------------------------------------------
extern "C" void kernel_launch(void* const* d_in, const int* in_sizes, int n_in,
                              void* d_out, int out_size)
{
    const float* se   = (const float*)d_in[0];
    const float* c0   = (const float*)d_in[1];
    const float* c1   = (const float*)d_in[2];
    const float* c2   = (const float*)d_in[3];
    const int*   i2c0 = (const int*)d_in[4];
    const int*   i2c1 = (const int*)d_in[5];
    const int*   i2c2 = (const int*)d_in[6];
    const int*   idx  = (const int*)d_in[7];
    const int*   neg  = (const int*)d_in[8];
    float*       out  = (float*)d_out;

    k_norm_pos<<<B, 96>>>(se, c0, c1, c2, i2c0, i2c1, i2c2, idx);
    dim3 g2(H, B / BT);
    k_sims<<<g2, 256>>>(c0, c1, c2);
    k_negloss<<<B, 256>>>(neg, c0, c1, c2);
    k_final<<<1, 256>>>(out);
}

// round 2
// speedup vs baseline: 1.2663x; 1.2663x over previous
#include <cuda_runtime.h>
#include <math.h>

#define B      256
#define NNEG   1000
#define H      3
#define D      128
#define NMIN   250
#define EPSF   1e-6f
#define BT     4            // samples per block
#define NBLK   (B / BT)     // 64 blocks
#define NTHR   512
#define NTASK  762          // 750 sim tasks + 12 pos tasks
#define SWEEPS 6            // 6 * 128 = 768 >= 762

__device__ float         g_partial[NBLK];
__device__ unsigned int  g_ticket = 0;

// ---------------- packed f32x2 helpers (sm_103a FFMA2 via PTX) ----------------
__device__ __forceinline__ unsigned long long pk2(float a, float b) {
    return (unsigned long long)__float_as_uint(a) |
           ((unsigned long long)__float_as_uint(b) << 32);
}
__device__ __forceinline__ void ffma2(unsigned long long& d,
                                      unsigned long long a,
                                      unsigned long long b) {
    asm("fma.rn.f32x2 %0, %1, %2, %0;" : "+l"(d) : "l"(a), "l"(b));
}
__device__ __forceinline__ float upsum(unsigned long long v) {
    return __uint_as_float((unsigned)v) + __uint_as_float((unsigned)(v >> 32));
}

__device__ __forceinline__ float warp_sum32(float v) {
#pragma unroll
    for (int o = 16; o > 0; o >>= 1) v += __shfl_xor_sync(0xffffffffu, v, o);
    return v;
}
// reduction across an 8-lane group (xor 1,2,4 stay within the group)
__device__ __forceinline__ float group_sum8(float v) {
    v += __shfl_xor_sync(0xffffffffu, v, 1);
    v += __shfl_xor_sync(0xffffffffu, v, 2);
    v += __shfl_xor_sync(0xffffffffu, v, 4);
    return v;
}

// rare fallback: direct half-sim for an id outside the hot range (never taken
// with this data distribution, kept for robustness)
__device__ __noinline__ float halfsim_fb(const float* __restrict__ cents, int id,
                                         const float* se_row) {
    const float* cv = cents + (long)id * D;
    float dot = 0.f, cs = 0.f;
    for (int k = 0; k < D; k++) {
        float c = cv[k];
        dot += c * se_row[k];
        cs  += c * c;
    }
    return (dot / fmaxf(sqrtf(cs), 1e-12f) + 1.0f) * 0.5f;
}

__global__ __launch_bounds__(NTHR, 1)
void hirl_fused(const float* __restrict__ se,
                const float* __restrict__ c0,
                const float* __restrict__ c1,
                const float* __restrict__ c2,
                const int* __restrict__ i2c0,
                const int* __restrict__ i2c1,
                const int* __restrict__ i2c2,
                const int* __restrict__ idx,
                const int* __restrict__ negid,
                float* __restrict__ out)
{
    __shared__ float4 s_se4[BT * H * 32];        // 12 rows x 128 floats (normalized)
    __shared__ float  s_sims[BT * H * NMIN];     // half-sims, [s][h][c]
    __shared__ int    s_poslab[BT * H];
    __shared__ float  s_psim[BT * H];
    __shared__ float  s_red[16][2];              // per-warp (sum, cnt) for phase C
    __shared__ float  s_tot[BT];
    __shared__ bool   s_amLast;

    const int tid  = threadIdx.x;
    const int warp = tid >> 5;
    const int lane = tid & 31;
    const int b0   = blockIdx.x * BT;

    // =================== Phase A: normalize se rows + pos labels ===================
    if (warp < BT * H) {
        int s = warp / H, h = warp - s * H;
        float4 v = ((const float4*)(se + ((long)(b0 + s) * H + h) * D))[lane];
        float ss = v.x * v.x + v.y * v.y + v.z * v.z + v.w * v.w;
        ss = warp_sum32(ss);
        float inv = 1.0f / fmaxf(sqrtf(ss), 1e-12f);
        v.x *= inv; v.y *= inv; v.z *= inv; v.w *= inv;
        s_se4[(s * H + h) * 32 + lane] = v;
    } else if (warp == 12 && lane < BT * H) {
        int s = lane / H, h = lane - s * H;
        int iv = idx[b0 + s];
        const int* p = (h == 0) ? i2c0 : ((h == 1) ? i2c1 : i2c2);
        s_poslab[lane] = p[iv];
    }
    __syncthreads();

    // =================== Phase B: half-sim table (+ pos sims) ===================
    // tasks: t<750 -> (h=t/250, c=t%250) sims for all 4 samples
    //        750<=t<762 -> positive-path dot for (s,h) = ((t-750)/3, (t-750)%3)
    {
        const int g   = lane >> 3;   // group 0..3
        const int sub = lane & 7;    // sub-lane 0..7
        const float* cptr[H] = { c0, c1, c2 };

#pragma unroll 1
        for (int sweep = 0; sweep < SWEEPS; sweep++) {
            int tbase = sweep * 128 + warp * 8 + g * 2;
            int   th[2], tc[2], posr[2];
            bool  valid[2], ispos[2];
#pragma unroll
            for (int c2 = 0; c2 < 2; c2++) {
                int t = tbase + c2;
                if (t < 750) {
                    int h = (t >= 500) ? 2 : ((t >= 250) ? 1 : 0);
                    th[c2] = h; tc[c2] = t - h * NMIN;
                    valid[c2] = true; ispos[c2] = false; posr[c2] = 0;
                } else if (t < NTASK) {
                    int i = t - 750;
                    int s = i / H, h = i - s * H;
                    th[c2] = h; tc[c2] = s_poslab[i];
                    valid[c2] = true; ispos[c2] = true; posr[c2] = s;
                } else {
                    th[c2] = 0; tc[c2] = 0;
                    valid[c2] = false; ispos[c2] = false; posr[c2] = 0;
                }
            }

            // load 16 floats per lane per task: k = 32*j + 4*sub + {0..3}
            float4 cv[2][4];
#pragma unroll
            for (int c2 = 0; c2 < 2; c2++) {
                const float4* cp = (const float4*)(cptr[th[c2]] + (long)tc[c2] * D);
#pragma unroll
                for (int j = 0; j < 4; j++)
                    cv[c2][j] = __ldg(cp + 8 * j + sub);
            }

            // centroid sumsq -> inv norm
            float inv[2];
#pragma unroll
            for (int c2 = 0; c2 < 2; c2++) {
                unsigned long long a = 0, b = 0;
#pragma unroll
                for (int j = 0; j < 4; j++) {
                    unsigned long long lo = pk2(cv[c2][j].x, cv[c2][j].y);
                    unsigned long long hi = pk2(cv[c2][j].z, cv[c2][j].w);
                    ffma2(a, lo, lo);
                    ffma2(b, hi, hi);
                }
                float cs = group_sum8(upsum(a) + upsum(b));
                inv[c2] = 1.0f / fmaxf(sqrtf(cs), 1e-12f);
            }

            // dots with the 4 samples' rows of hierarchy th[c2]
#pragma unroll
            for (int r = 0; r < BT; r++) {
#pragma unroll
                for (int c2 = 0; c2 < 2; c2++) {
                    int row = r * H + th[c2];
                    unsigned long long a = 0, b = 0;
#pragma unroll
                    for (int j = 0; j < 4; j++) {
                        float4 sv = s_se4[row * 32 + 8 * j + sub];
                        ffma2(a, pk2(sv.x, sv.y), pk2(cv[c2][j].x, cv[c2][j].y));
                        ffma2(b, pk2(sv.z, sv.w), pk2(cv[c2][j].z, cv[c2][j].w));
                    }
                    float dot = group_sum8(upsum(a) + upsum(b));
                    if (sub == 0 && valid[c2]) {
                        float sim = (dot * inv[c2] + 1.0f) * 0.5f;
                        if (!ispos[c2])
                            s_sims[row * NMIN + tc[c2]] = sim;
                        else if (r == posr[c2])
                            s_psim[row] = sim;   // row = s*H + h
                    }
                }
            }
        }
    }
    __syncthreads();

    // =================== Phase C: negative losses ===================
    {
        const int s  = tid >> 7;       // sample 0..3
        const int lg = tid & 127;
        const int b  = b0 + s;
        const float* simrow = &s_sims[s * H * NMIN];
        const int pl0 = s_poslab[s * H + 0];
        const int pl1 = s_poslab[s * H + 1];
        const int pl2 = s_poslab[s * H + 2];

        float sum = 0.f, cnt = 0.f;
        for (int n = lg; n < NNEG; n += 128) {
            const int* q = negid + ((long)b * NNEG + n) * H;
            int i0 = q[0], i1 = q[1], i2 = q[2];
            float p0 = (i0 < NMIN) ? simrow[0 * NMIN + i0]
                     : halfsim_fb(c0, i0, (const float*)&s_se4[(s * H + 0) * 32]);
            float p1 = (i1 < NMIN) ? simrow[1 * NMIN + i1]
                     : halfsim_fb(c1, i1, (const float*)&s_se4[(s * H + 1) * 32]);
            float p2 = (i2 < NMIN) ? simrow[2 * NMIN + i2]
                     : halfsim_fb(c2, i2, (const float*)&s_se4[(s * H + 2) * 32]);
            float p = p0 * p1 * p2;
            if ((i0 != pl0) | (i1 != pl1) | (i2 != pl2)) {
                sum += -logf(1.0f - p + EPSF);
                cnt += 1.0f;
            }
        }
        sum = warp_sum32(sum);
        cnt = warp_sum32(cnt);
        if (lane == 0) { s_red[warp][0] = sum; s_red[warp][1] = cnt; }
    }
    __syncthreads();

    if (tid < BT) {
        int s = tid;
        float sum = 0.f, cnt = 0.f;
#pragma unroll
        for (int w = 0; w < 4; w++) {
            sum += s_red[s * 4 + w][0];
            cnt += s_red[s * 4 + w][1];
        }
        float pprod  = s_psim[s * H + 0] * s_psim[s * H + 1] * s_psim[s * H + 2];
        float ploss  = -logf(pprod + EPSF);
        s_tot[s] = ploss + sum / (cnt + EPSF);
    }
    __syncthreads();
    if (tid == 0)
        g_partial[blockIdx.x] = s_tot[0] + s_tot[1] + s_tot[2] + s_tot[3];

    // =================== Final: last block reduces 64 partials ===================
    if (tid == 0) {
        __threadfence();
        s_amLast = (atomicAdd(&g_ticket, 1u) == NBLK - 1);
    }
    __syncthreads();
    if (s_amLast && warp == 0) {
        volatile float* gp = g_partial;
        float v = gp[lane] + gp[lane + 32];
        v = warp_sum32(v);
        if (lane == 0) {
            out[0] = v * (1.0f / (2.0f * (float)B));
            g_ticket = 0;
        }
    }
}

extern "C" void kernel_launch(void* const* d_in, const int* in_sizes, int n_in,
                              void* d_out, int out_size)
{
    const float* se   = (const float*)d_in[0];
    const float* c0   = (const float*)d_in[1];
    const float* c1   = (const float*)d_in[2];
    const float* c2   = (const float*)d_in[3];
    const int*   i2c0 = (const int*)d_in[4];
    const int*   i2c1 = (const int*)d_in[5];
    const int*   i2c2 = (const int*)d_in[6];
    const int*   idx  = (const int*)d_in[7];
    const int*   neg  = (const int*)d_in[8];
    float*       out  = (float*)d_out;

    hirl_fused<<<NBLK, NTHR>>>(se, c0, c1, c2, i2c0, i2c1, i2c2, idx, neg, out);
}

// round 4
// speedup vs baseline: 1.5268x; 1.2057x over previous
#include <cuda_runtime.h>
#include <math.h>

#define B      256
#define NNEG   1000
#define H      3
#define D      128
#define NMIN   250
#define EPSF   1e-6f
#define BT     4                 // samples per block
#define NBLK   (B / BT)          // 64 blocks
#define NTHR   512               // 16 warps
#define CHUNKS_PER_H 63          // ceil(250/4)
#define SIM_CHUNKS   (H * CHUNKS_PER_H)   // 189
#define ROUNDS 12                // 16 warps * 12 = 192 chunks (189 sim + 3 pos)

__device__ float        g_partial[NBLK];
__device__ unsigned int g_ticket = 0;

// ---- packed f32x2 FMA (sm_103a FFMA2; operands come pre-packed from ld.128) ----
__device__ __forceinline__ void ffma2(unsigned long long& d,
                                      unsigned long long a,
                                      unsigned long long b) {
    asm("fma.rn.f32x2 %0, %1, %2, %0;" : "+l"(d) : "l"(a), "l"(b));
}
__device__ __forceinline__ float upsum(unsigned long long v) {
    return __uint_as_float((unsigned)v) + __uint_as_float((unsigned)(v >> 32));
}
// sum across an 8-lane group (xor 1,2,4 stay within the group)
__device__ __forceinline__ float group_sum8(float v) {
    v += __shfl_xor_sync(0xffffffffu, v, 1);
    v += __shfl_xor_sync(0xffffffffu, v, 2);
    v += __shfl_xor_sync(0xffffffffu, v, 4);
    return v;
}
__device__ __forceinline__ float warp_sum32(float v) {
#pragma unroll
    for (int o = 16; o > 0; o >>= 1) v += __shfl_xor_sync(0xffffffffu, v, o);
    return v;
}

// rare fallback (never taken: neg ids < NMIN by construction)
__device__ __noinline__ float halfsim_fb(const float* __restrict__ cents, int id,
                                         const float* se_row) {
    const float* cv = cents + (long)id * D;
    float dot = 0.f, cs = 0.f;
    for (int k = 0; k < D; k++) { float c = cv[k]; dot += c * se_row[k]; cs += c * c; }
    return (dot * rsqrtf(fmaxf(cs, 1e-24f)) + 1.0f) * 0.5f;
}

__global__ __launch_bounds__(NTHR, 1)
void hirl_fused(const float* __restrict__ se,
                const float* __restrict__ c0,
                const float* __restrict__ c1,
                const float* __restrict__ c2,
                const int* __restrict__ i2c0,
                const int* __restrict__ i2c1,
                const int* __restrict__ i2c2,
                const int* __restrict__ idx,
                const int* __restrict__ negid,
                float* __restrict__ out)
{
    __shared__ float4 s_se4[BT * H * 32];     // 12 normalized rows x 128 floats
    __shared__ float  s_sims[BT * H * NMIN];  // [s][h][c]
    __shared__ int    s_poslab[BT * H];
    __shared__ float  s_psim[BT * H];
    __shared__ float  s_red[16][2];
    __shared__ float  s_tot[BT];
    __shared__ bool   s_amLast;

    const int tid  = threadIdx.x;
    const int warp = tid >> 5;
    const int lane = tid & 31;
    const int b0   = blockIdx.x * BT;

    // ================= Phase A: normalize se rows + positive labels =================
    if (warp < BT * H) {
        int s = warp / H, h = warp - s * H;
        float4 v = ((const float4*)(se + ((long)(b0 + s) * H + h) * D))[lane];
        float ss = warp_sum32(v.x * v.x + v.y * v.y + v.z * v.z + v.w * v.w);
        float inv = rsqrtf(fmaxf(ss, 1e-24f));
        v.x *= inv; v.y *= inv; v.z *= inv; v.w *= inv;
        s_se4[(s * H + h) * 32 + lane] = v;
    } else if (warp == 12 && lane < BT * H) {
        int s = lane / H, h = lane - s * H;
        const int* p = (h == 0) ? i2c0 : ((h == 1) ? i2c1 : i2c2);
        s_poslab[lane] = p[idx[b0 + s]];
    }
    __syncthreads();

    // ================= Phase B: half-sim table + positive sims =================
    // chunk = warp + 16*r in [0,192). chunk<189: h = chunk/63, 4 centroids (one per
    // 8-lane group), dots vs all 4 samples. chunk>=189: positive dots for
    // h = chunk-189, group g handles sample g. Warp-uniform h -> se rows cached
    // in registers, reloaded only when h changes (<=3 times per warp).
    {
        const int g   = lane >> 3;
        const int sub = lane & 7;
        const float* cptr[H] = { c0, c1, c2 };

        ulonglong2 seR[BT][4];     // se rows (s=0..3) of current h, 16 floats/lane
        int hcur = -1;

#pragma unroll 1
        for (int r = 0; r < ROUNDS; r++) {
            int  chunk = warp + 16 * r;
            bool isPos = (chunk >= SIM_CHUNKS);
            int  h     = isPos ? (chunk - SIM_CHUNKS) : (chunk / CHUNKS_PER_H);

            if (h != hcur) {
                hcur = h;
#pragma unroll
                for (int s2 = 0; s2 < BT; s2++)
#pragma unroll
                    for (int j = 0; j < 4; j++)
                        seR[s2][j] =
                            ((const ulonglong2*)&s_se4[(s2 * H + h) * 32])[j * 8 + sub];
            }

            int c = isPos ? s_poslab[g * H + h]
                          : (chunk - h * CHUNKS_PER_H) * 4 + g;
            bool valid = isPos || (c < NMIN);
            int  cc    = valid ? c : 0;

            const ulonglong2* cp = (const ulonglong2*)(cptr[h] + (long)cc * D);
            ulonglong2 cv[4];
#pragma unroll
            for (int j = 0; j < 4; j++) cv[j] = cp[j * 8 + sub];

            unsigned long long ss = 0, d0 = 0, d1 = 0, d2 = 0, d3 = 0;
#pragma unroll
            for (int j = 0; j < 4; j++) {
                ffma2(ss, cv[j].x, cv[j].x); ffma2(ss, cv[j].y, cv[j].y);
                ffma2(d0, seR[0][j].x, cv[j].x); ffma2(d0, seR[0][j].y, cv[j].y);
                ffma2(d1, seR[1][j].x, cv[j].x); ffma2(d1, seR[1][j].y, cv[j].y);
                ffma2(d2, seR[2][j].x, cv[j].x); ffma2(d2, seR[2][j].y, cv[j].y);
                ffma2(d3, seR[3][j].x, cv[j].x); ffma2(d3, seR[3][j].y, cv[j].y);
            }
            // 5 independent 3-shfl reduction chains (pipeline across warps)
            float ssf = group_sum8(upsum(ss));
            float f0  = group_sum8(upsum(d0));
            float f1  = group_sum8(upsum(d1));
            float f2  = group_sum8(upsum(d2));
            float f3  = group_sum8(upsum(d3));
            float inv5 = 0.5f * rsqrtf(fmaxf(ssf, 1e-24f));

            if (sub == 0 && valid) {
                if (!isPos) {
                    s_sims[(0 * H + h) * NMIN + c] = __fmaf_rn(f0, inv5, 0.5f);
                    s_sims[(1 * H + h) * NMIN + c] = __fmaf_rn(f1, inv5, 0.5f);
                    s_sims[(2 * H + h) * NMIN + c] = __fmaf_rn(f2, inv5, 0.5f);
                    s_sims[(3 * H + h) * NMIN + c] = __fmaf_rn(f3, inv5, 0.5f);
                } else {
                    float dd = (g == 0) ? f0 : (g == 1) ? f1 : (g == 2) ? f2 : f3;
                    s_psim[g * H + h] = __fmaf_rn(dd, inv5, 0.5f);
                }
            }
        }
    }
    __syncthreads();

    // ================= Phase C: negative losses =================
    {
        const int s  = tid >> 7;          // sample 0..3
        const int lg = tid & 127;
        const int b  = b0 + s;
        const float* simrow = &s_sims[s * H * NMIN];
        const int pl0 = s_poslab[s * H + 0];
        const int pl1 = s_poslab[s * H + 1];
        const int pl2 = s_poslab[s * H + 2];

        float sum = 0.f, cnt = 0.f;
        for (int n = lg; n < NNEG; n += 128) {
            const int* q = negid + ((long)b * NNEG + n) * H;
            int i0 = q[0], i1 = q[1], i2 = q[2];
            float p0 = (i0 < NMIN) ? simrow[0 * NMIN + i0]
                     : halfsim_fb(c0, i0, (const float*)&s_se4[(s * H + 0) * 32]);
            float p1 = (i1 < NMIN) ? simrow[1 * NMIN + i1]
                     : halfsim_fb(c1, i1, (const float*)&s_se4[(s * H + 1) * 32]);
            float p2 = (i2 < NMIN) ? simrow[2 * NMIN + i2]
                     : halfsim_fb(c2, i2, (const float*)&s_se4[(s * H + 2) * 32]);
            float p = p0 * p1 * p2;
            if ((i0 != pl0) | (i1 != pl1) | (i2 != pl2)) {
                sum += -__logf(1.0f - p + EPSF);
                cnt += 1.0f;
            }
        }
        sum = warp_sum32(sum);
        cnt = warp_sum32(cnt);
        if (lane == 0) { s_red[warp][0] = sum; s_red[warp][1] = cnt; }
    }
    __syncthreads();

    if (tid < BT) {
        int s = tid;
        float sum = 0.f, cnt = 0.f;
#pragma unroll
        for (int w = 0; w < 4; w++) { sum += s_red[s * 4 + w][0]; cnt += s_red[s * 4 + w][1]; }
        float pprod = s_psim[s * H + 0] * s_psim[s * H + 1] * s_psim[s * H + 2];
        s_tot[s] = -__logf(pprod + EPSF) + sum / (cnt + EPSF);
    }
    __syncthreads();
    if (tid == 0)
        g_partial[blockIdx.x] = s_tot[0] + s_tot[1] + s_tot[2] + s_tot[3];

    // ================= Final: last block reduces 64 partials =================
    if (tid == 0) {
        __threadfence();
        s_amLast = (atomicAdd(&g_ticket, 1u) == NBLK - 1);
    }
    __syncthreads();
    if (s_amLast && warp == 0) {
        volatile float* gp = g_partial;
        float v = gp[lane] + gp[lane + 32];
        v = warp_sum32(v);
        if (lane == 0) {
            out[0] = v * (1.0f / (2.0f * (float)B));
            g_ticket = 0;
        }
    }
}

extern "C" void kernel_launch(void* const* d_in, const int* in_sizes, int n_in,
                              void* d_out, int out_size)
{
    const float* se   = (const float*)d_in[0];
    const float* c0   = (const float*)d_in[1];
    const float* c1   = (const float*)d_in[2];
    const float* c2   = (const float*)d_in[3];
    const int*   i2c0 = (const int*)d_in[4];
    const int*   i2c1 = (const int*)d_in[5];
    const int*   i2c2 = (const int*)d_in[6];
    const int*   idx  = (const int*)d_in[7];
    const int*   neg  = (const int*)d_in[8];
    float*       out  = (float*)d_out;

    hirl_fused<<<NBLK, NTHR>>>(se, c0, c1, c2, i2c0, i2c1, i2c2, idx, neg, out);
}

// round 5
// speedup vs baseline: 1.9677x; 1.2888x over previous
#include <cuda_runtime.h>
#include <math.h>

#define B      256
#define NNEG   1000
#define H      3
#define D      128
#define NMIN   250
#define EPSF   1e-6f
#define BT     2                 // samples per block
#define NBLK   (B / BT)          // 128 blocks
#define NTHR   512               // 16 warps
#define CHUNKS_PER_H 63          // ceil(250/4)
#define SIM_CHUNKS   (H * CHUNKS_PER_H)   // 189
#define ROUNDS 12                // 16 warps * 12 = 192 chunks (189 sim + 3 pos)

__device__ float        g_partial[NBLK];
__device__ unsigned int g_ticket = 0;

// ---- packed f32x2 FMA (sm_103a FFMA2; operands come pre-packed from ld.128) ----
__device__ __forceinline__ void ffma2(unsigned long long& d,
                                      unsigned long long a,
                                      unsigned long long b) {
    asm("fma.rn.f32x2 %0, %1, %2, %0;" : "+l"(d) : "l"(a), "l"(b));
}
__device__ __forceinline__ float upsum(unsigned long long v) {
    return __uint_as_float((unsigned)v) + __uint_as_float((unsigned)(v >> 32));
}
// sum across an 8-lane group (xor 1,2,4 stay within the group)
__device__ __forceinline__ float group_sum8(float v) {
    v += __shfl_xor_sync(0xffffffffu, v, 1);
    v += __shfl_xor_sync(0xffffffffu, v, 2);
    v += __shfl_xor_sync(0xffffffffu, v, 4);
    return v;
}
__device__ __forceinline__ float warp_sum32(float v) {
#pragma unroll
    for (int o = 16; o > 0; o >>= 1) v += __shfl_xor_sync(0xffffffffu, v, o);
    return v;
}

// rare fallback (never taken: neg ids < NMIN by construction)
__device__ __noinline__ float halfsim_fb(const float* __restrict__ cents, int id,
                                         const float* se_row) {
    const float* cv = cents + (long)id * D;
    float dot = 0.f, cs = 0.f;
    for (int k = 0; k < D; k++) { float c = cv[k]; dot += c * se_row[k]; cs += c * c; }
    return (dot * rsqrtf(fmaxf(cs, 1e-24f)) + 1.0f) * 0.5f;
}

struct Task { int h, c; bool valid, isPos; };

__device__ __forceinline__ Task make_task(int chunk, int g,
                                          const int* s_poslab) {
    Task t;
    t.isPos = (chunk >= SIM_CHUNKS);
    if (t.isPos) {
        t.h = chunk - SIM_CHUNKS;
        t.valid = (g < BT);
        t.c = t.valid ? s_poslab[g * H + t.h] : 0;
    } else {
        t.h = chunk / CHUNKS_PER_H;
        int c = (chunk - t.h * CHUNKS_PER_H) * 4 + g;
        t.valid = (c < NMIN);
        t.c = t.valid ? c : 0;
    }
    return t;
}

__global__ __launch_bounds__(NTHR, 1)
void hirl_fused(const float* __restrict__ se,
                const float* __restrict__ c0,
                const float* __restrict__ c1,
                const float* __restrict__ c2,
                const int* __restrict__ i2c0,
                const int* __restrict__ i2c1,
                const int* __restrict__ i2c2,
                const int* __restrict__ idx,
                const int* __restrict__ negid,
                float* __restrict__ out)
{
    __shared__ float4 s_se4[BT * H * 32];     // 6 normalized rows x 128 floats
    __shared__ float  s_sims[BT * H * NMIN];  // [s][h][c]
    __shared__ int    s_poslab[BT * H];
    __shared__ float  s_psim[BT * H];
    __shared__ float  s_red[16][2];
    __shared__ float  s_tot[BT];
    __shared__ bool   s_amLast;

    const int tid  = threadIdx.x;
    const int warp = tid >> 5;
    const int lane = tid & 31;
    const int b0   = blockIdx.x * BT;

    // ================= Phase A: normalize se rows + positive labels =================
    if (warp < BT * H) {
        int s = warp / H, h = warp - s * H;
        float4 v = ((const float4*)(se + ((long)(b0 + s) * H + h) * D))[lane];
        float ss = warp_sum32(v.x * v.x + v.y * v.y + v.z * v.z + v.w * v.w);
        float inv = rsqrtf(fmaxf(ss, 1e-24f));
        v.x *= inv; v.y *= inv; v.z *= inv; v.w *= inv;
        s_se4[(s * H + h) * 32 + lane] = v;
    } else if (warp == 6 && lane < BT * H) {
        int s = lane / H, h = lane - s * H;
        const int* p = (h == 0) ? i2c0 : ((h == 1) ? i2c1 : i2c2);
        s_poslab[lane] = p[idx[b0 + s]];
    }
    __syncthreads();

    // ================= Phase B: half-sim table + positive sims =================
    // chunk = warp + 16*r in [0,192). Warp-uniform h; 4 centroids per chunk
    // (one per 8-lane group). Centroid loads for round r+1 are issued before
    // round r's reduction chain (software pipeline) to hide L2 latency.
    {
        const int g   = lane >> 3;
        const int sub = lane & 7;
        const float* cptr[H] = { c0, c1, c2 };

        ulonglong2 seR[BT][4];     // se rows of current h, 16 floats/lane
        int hcur = -1;

        Task tA = make_task(warp, g, s_poslab);
        ulonglong2 cvA[4];
        {
            const ulonglong2* cp = (const ulonglong2*)(cptr[tA.h] + (long)tA.c * D);
#pragma unroll
            for (int j = 0; j < 4; j++) cvA[j] = cp[j * 8 + sub];
        }

#pragma unroll 1
        for (int r = 0; r < ROUNDS; r++) {
            // prefetch next round
            Task tB;
            ulonglong2 cvB[4];
            if (r + 1 < ROUNDS) {
                tB = make_task(warp + 16 * (r + 1), g, s_poslab);
                const ulonglong2* cp =
                    (const ulonglong2*)(cptr[tB.h] + (long)tB.c * D);
#pragma unroll
                for (int j = 0; j < 4; j++) cvB[j] = cp[j * 8 + sub];
            }

            if (tA.h != hcur) {
                hcur = tA.h;
#pragma unroll
                for (int s2 = 0; s2 < BT; s2++)
#pragma unroll
                    for (int j = 0; j < 4; j++)
                        seR[s2][j] = ((const ulonglong2*)
                            &s_se4[(s2 * H + hcur) * 32])[j * 8 + sub];
            }

            unsigned long long ss = 0, d0 = 0, d1 = 0;
#pragma unroll
            for (int j = 0; j < 4; j++) {
                ffma2(ss, cvA[j].x, cvA[j].x); ffma2(ss, cvA[j].y, cvA[j].y);
                ffma2(d0, seR[0][j].x, cvA[j].x); ffma2(d0, seR[0][j].y, cvA[j].y);
                ffma2(d1, seR[1][j].x, cvA[j].x); ffma2(d1, seR[1][j].y, cvA[j].y);
            }
            float ssf = group_sum8(upsum(ss));
            float f0  = group_sum8(upsum(d0));
            float f1  = group_sum8(upsum(d1));
            float inv5 = 0.5f * rsqrtf(fmaxf(ssf, 1e-24f));

            if (sub == 0 && tA.valid) {
                if (!tA.isPos) {
                    s_sims[(0 * H + tA.h) * NMIN + tA.c] = __fmaf_rn(f0, inv5, 0.5f);
                    s_sims[(1 * H + tA.h) * NMIN + tA.c] = __fmaf_rn(f1, inv5, 0.5f);
                } else {
                    s_psim[g * H + tA.h] =
                        __fmaf_rn((g == 0) ? f0 : f1, inv5, 0.5f);
                }
            }

            tA = tB;
#pragma unroll
            for (int j = 0; j < 4; j++) cvA[j] = cvB[j];
        }
    }
    __syncthreads();

    // ================= Phase C: negative losses =================
    {
        const int s  = tid >> 8;          // sample 0..1
        const int lg = tid & 255;
        const int b  = b0 + s;
        const float* simrow = &s_sims[s * H * NMIN];
        const int pl0 = s_poslab[s * H + 0];
        const int pl1 = s_poslab[s * H + 1];
        const int pl2 = s_poslab[s * H + 2];

        float sum = 0.f, cnt = 0.f;
#pragma unroll
        for (int it = 0; it < 4; it++) {
            int n = lg + it * 256;
            if (n < NNEG) {
                const int* q = negid + ((long)b * NNEG + n) * H;
                int i0 = q[0], i1 = q[1], i2 = q[2];
                float p0 = (i0 < NMIN) ? simrow[0 * NMIN + i0]
                         : halfsim_fb(c0, i0, (const float*)&s_se4[(s * H + 0) * 32]);
                float p1 = (i1 < NMIN) ? simrow[1 * NMIN + i1]
                         : halfsim_fb(c1, i1, (const float*)&s_se4[(s * H + 1) * 32]);
                float p2 = (i2 < NMIN) ? simrow[2 * NMIN + i2]
                         : halfsim_fb(c2, i2, (const float*)&s_se4[(s * H + 2) * 32]);
                float p = p0 * p1 * p2;
                if ((i0 != pl0) | (i1 != pl1) | (i2 != pl2)) {
                    sum += -__logf(1.0f - p + EPSF);
                    cnt += 1.0f;
                }
            }
        }
        sum = warp_sum32(sum);
        cnt = warp_sum32(cnt);
        if (lane == 0) { s_red[warp][0] = sum; s_red[warp][1] = cnt; }
    }
    __syncthreads();

    if (tid < BT) {
        int s = tid;
        float sum = 0.f, cnt = 0.f;
#pragma unroll
        for (int w = 0; w < 8; w++) { sum += s_red[s * 8 + w][0]; cnt += s_red[s * 8 + w][1]; }
        float pprod = s_psim[s * H + 0] * s_psim[s * H + 1] * s_psim[s * H + 2];
        s_tot[s] = -__logf(pprod + EPSF) + sum / (cnt + EPSF);
    }
    __syncthreads();
    if (tid == 0)
        g_partial[blockIdx.x] = s_tot[0] + s_tot[1];

    // ================= Final: last block reduces 128 partials =================
    if (tid == 0) {
        __threadfence();
        s_amLast = (atomicAdd(&g_ticket, 1u) == NBLK - 1);
    }
    __syncthreads();
    if (s_amLast && warp == 0) {
        volatile float* gp = g_partial;
        float v = gp[lane] + gp[lane + 32] + gp[lane + 64] + gp[lane + 96];
        v = warp_sum32(v);
        if (lane == 0) {
            out[0] = v * (1.0f / (2.0f * (float)B));
            g_ticket = 0;
        }
    }
}

extern "C" void kernel_launch(void* const* d_in, const int* in_sizes, int n_in,
                              void* d_out, int out_size)
{
    const float* se   = (const float*)d_in[0];
    const float* c0   = (const float*)d_in[1];
    const float* c1   = (const float*)d_in[2];
    const float* c2   = (const float*)d_in[3];
    const int*   i2c0 = (const int*)d_in[4];
    const int*   i2c1 = (const int*)d_in[5];
    const int*   i2c2 = (const int*)d_in[6];
    const int*   idx  = (const int*)d_in[7];
    const int*   neg  = (const int*)d_in[8];
    float*       out  = (float*)d_out;

    hirl_fused<<<NBLK, NTHR>>>(se, c0, c1, c2, i2c0, i2c1, i2c2, idx, neg, out);
}

// round 9
// speedup vs baseline: 2.1686x; 1.1021x over previous
#include <cuda_runtime.h>
#include <math.h>

#define B      256
#define NNEG   1000
#define H      3
#define D      128
#define NMIN   250
#define EPSF   1e-6f
#define BT     2                 // samples per block
#define NBLK   (B / BT)          // 128 blocks
#define NTHR   512               // 16 warps
#define ROUNDS 6                 // 96 chunks = 16 warps * 6 rounds; 8 c-slots/chunk

__device__ float        g_partial[NBLK];
__device__ unsigned int g_ticket = 0;

// ---- packed f32x2 FMA (sm_103a FFMA2; operands pre-packed by 128-bit loads) ----
__device__ __forceinline__ void ffma2(unsigned long long& d,
                                      unsigned long long a,
                                      unsigned long long b) {
    asm("fma.rn.f32x2 %0, %1, %2, %0;" : "+l"(d) : "l"(a), "l"(b));
}
__device__ __forceinline__ float upsum(unsigned long long v) {
    return __uint_as_float((unsigned)v) + __uint_as_float((unsigned)(v >> 32));
}
// sum across an 8-lane group (xor 1,2,4 stay within the group)
__device__ __forceinline__ float group_sum8(float v) {
    v += __shfl_xor_sync(0xffffffffu, v, 1);
    v += __shfl_xor_sync(0xffffffffu, v, 2);
    v += __shfl_xor_sync(0xffffffffu, v, 4);
    return v;
}
__device__ __forceinline__ float warp_sum32(float v) {
#pragma unroll
    for (int o = 16; o > 0; o >>= 1) v += __shfl_xor_sync(0xffffffffu, v, o);
    return v;
}

// rare fallback (never taken: neg ids < NMIN by construction)
__device__ __noinline__ float halfsim_fb(const float* __restrict__ cents, int id,
                                         const float* se_row) {
    const float* cv = cents + (long)id * D;
    float dot = 0.f, cs = 0.f;
    for (int k = 0; k < D; k++) { float c = cv[k]; dot += c * se_row[k]; cs += c * c; }
    return (dot * rsqrtf(fmaxf(cs, 1e-24f)) + 1.0f) * 0.5f;
}

__global__ __launch_bounds__(NTHR, 1)
void hirl_fused(const float* __restrict__ se,
                const float* __restrict__ c0,
                const float* __restrict__ c1,
                const float* __restrict__ c2,
                const int* __restrict__ i2c0,
                const int* __restrict__ i2c1,
                const int* __restrict__ i2c2,
                const int* __restrict__ idx,
                const int* __restrict__ negid,
                float* __restrict__ out)
{
    __shared__ float4 s_se4[BT * H * 32];     // 6 normalized rows x 128 floats
    __shared__ float  s_sims[BT * H * NMIN];  // [s][h][c]
    __shared__ int    s_poslab[BT * H];
    __shared__ float  s_psim[BT * H];
    __shared__ float  s_red[16][2];
    __shared__ float  s_tot[BT];
    __shared__ bool   s_amLast;

    const int tid  = threadIdx.x;
    const int warp = tid >> 5;
    const int lane = tid & 31;
    const int b0   = blockIdx.x * BT;

    // ================= Phase A: normalize se rows + positive labels =================
    if (warp < BT * H) {
        int s = warp / H, h = warp - s * H;
        float4 v = ((const float4*)(se + ((long)(b0 + s) * H + h) * D))[lane];
        float ss = warp_sum32(v.x * v.x + v.y * v.y + v.z * v.z + v.w * v.w);
        float inv = rsqrtf(fmaxf(ss, 1e-24f));
        v.x *= inv; v.y *= inv; v.z *= inv; v.w *= inv;
        s_se4[(s * H + h) * 32 + lane] = v;
    } else if (warp == 6 && lane < BT * H) {
        int s = lane / H, h = lane - s * H;
        const int* p = (h == 0) ? i2c0 : ((h == 1) ? i2c1 : i2c2);
        s_poslab[lane] = p[idx[b0 + s]];
    }
    __syncthreads();

    // ================= Phase B: half-sim table + positive sims =================
    // chunkid = r*16 + warp in [0,96): h = chunkid/32, cbase = (chunkid%32)*8.
    // Each 8-lane group g handles c = cbase+2g and cbase+2g+1 (2 tasks -> 6
    // independent FFMA chains + 6 independent 3-SHFL reductions per round).
    // Ghost slots c==250 / c==251 carry the positive-path dots (s=0 / s=1).
    {
        const int g   = lane >> 3;
        const int sub = lane & 7;
        const float* cptr[H] = { c0, c1, c2 };

        ulonglong2 seR[BT][4];     // se rows of current h, 16 floats/lane
        int hcur = -1;

#pragma unroll 1
        for (int r = 0; r < ROUNDS; r++) {
            int chunkid = r * 16 + warp;       // 0..95
            int h       = chunkid >> 5;        // 0..2, warp-uniform
            int cbase   = (chunkid & 31) * 8;

            if (h != hcur) {
                hcur = h;
#pragma unroll
                for (int s2 = 0; s2 < BT; s2++)
#pragma unroll
                    for (int j = 0; j < 4; j++)
                        seR[s2][j] = ((const ulonglong2*)
                            &s_se4[(s2 * H + hcur) * 32])[j * 8 + sub];
            }

            const int cA = cbase + g * 2;
            const int cB = cA + 1;
            // task A
            bool vA = (cA < NMIN + BT);
            bool pA = (cA >= NMIN) & vA;
            int  idA = vA ? (pA ? s_poslab[(cA - NMIN) * H + h] : cA) : 0;
            // task B
            bool vB = (cB < NMIN + BT);
            bool pB = (cB >= NMIN) & vB;
            int  idB = vB ? (pB ? s_poslab[(cB - NMIN) * H + h] : cB) : 0;

            const ulonglong2* cpA = (const ulonglong2*)(cptr[h] + (long)idA * D);
            const ulonglong2* cpB = (const ulonglong2*)(cptr[h] + (long)idB * D);
            ulonglong2 cvA[4], cvB[4];
#pragma unroll
            for (int j = 0; j < 4; j++) { cvA[j] = cpA[j * 8 + sub];
                                          cvB[j] = cpB[j * 8 + sub]; }

            unsigned long long ssA = 0, d0A = 0, d1A = 0;
            unsigned long long ssB = 0, d0B = 0, d1B = 0;
#pragma unroll
            for (int j = 0; j < 4; j++) {
                ffma2(ssA, cvA[j].x, cvA[j].x); ffma2(ssA, cvA[j].y, cvA[j].y);
                ffma2(d0A, seR[0][j].x, cvA[j].x); ffma2(d0A, seR[0][j].y, cvA[j].y);
                ffma2(d1A, seR[1][j].x, cvA[j].x); ffma2(d1A, seR[1][j].y, cvA[j].y);
                ffma2(ssB, cvB[j].x, cvB[j].x); ffma2(ssB, cvB[j].y, cvB[j].y);
                ffma2(d0B, seR[0][j].x, cvB[j].x); ffma2(d0B, seR[0][j].y, cvB[j].y);
                ffma2(d1B, seR[1][j].x, cvB[j].x); ffma2(d1B, seR[1][j].y, cvB[j].y);
            }
            // 6 independent 3-shfl reduction chains
            float sfA = group_sum8(upsum(ssA));
            float f0A = group_sum8(upsum(d0A));
            float f1A = group_sum8(upsum(d1A));
            float sfB = group_sum8(upsum(ssB));
            float f0B = group_sum8(upsum(d0B));
            float f1B = group_sum8(upsum(d1B));
            float invA = 0.5f * rsqrtf(fmaxf(sfA, 1e-24f));
            float invB = 0.5f * rsqrtf(fmaxf(sfB, 1e-24f));

            if (sub == 0) {
                if (vA) {
                    if (!pA) {
                        s_sims[(0 * H + h) * NMIN + cA] = __fmaf_rn(f0A, invA, 0.5f);
                        s_sims[(1 * H + h) * NMIN + cA] = __fmaf_rn(f1A, invA, 0.5f);
                    } else {
                        int s2 = cA - NMIN;
                        s_psim[s2 * H + h] =
                            __fmaf_rn((s2 == 0) ? f0A : f1A, invA, 0.5f);
                    }
                }
                if (vB) {
                    if (!pB) {
                        s_sims[(0 * H + h) * NMIN + cB] = __fmaf_rn(f0B, invB, 0.5f);
                        s_sims[(1 * H + h) * NMIN + cB] = __fmaf_rn(f1B, invB, 0.5f);
                    } else {
                        int s2 = cB - NMIN;
                        s_psim[s2 * H + h] =
                            __fmaf_rn((s2 == 0) ? f0B : f1B, invB, 0.5f);
                    }
                }
            }
        }
    }
    __syncthreads();

    // ================= Phase C: negative losses =================
    {
        const int s  = tid >> 8;          // sample 0..1
        const int lg = tid & 255;
        const int b  = b0 + s;
        const float* simrow = &s_sims[s * H * NMIN];
        const int pl0 = s_poslab[s * H + 0];
        const int pl1 = s_poslab[s * H + 1];
        const int pl2 = s_poslab[s * H + 2];

        float sum = 0.f, cnt = 0.f;
#pragma unroll
        for (int it = 0; it < 4; it++) {
            int n = lg + it * 256;
            if (n < NNEG) {
                const int* q = negid + ((long)b * NNEG + n) * H;
                int i0 = q[0], i1 = q[1], i2 = q[2];
                float p0 = (i0 < NMIN) ? simrow[0 * NMIN + i0]
                         : halfsim_fb(c0, i0, (const float*)&s_se4[(s * H + 0) * 32]);
                float p1 = (i1 < NMIN) ? simrow[1 * NMIN + i1]
                         : halfsim_fb(c1, i1, (const float*)&s_se4[(s * H + 1) * 32]);
                float p2 = (i2 < NMIN) ? simrow[2 * NMIN + i2]
                         : halfsim_fb(c2, i2, (const float*)&s_se4[(s * H + 2) * 32]);
                float p = p0 * p1 * p2;
                if ((i0 != pl0) | (i1 != pl1) | (i2 != pl2)) {
                    sum += -__logf(1.0f - p + EPSF);
                    cnt += 1.0f;
                }
            }
        }
        sum = warp_sum32(sum);
        cnt = warp_sum32(cnt);
        if (lane == 0) { s_red[warp][0] = sum; s_red[warp][1] = cnt; }
    }
    __syncthreads();

    if (tid < BT) {
        int s = tid;
        float sum = 0.f, cnt = 0.f;
#pragma unroll
        for (int w = 0; w < 8; w++) { sum += s_red[s * 8 + w][0]; cnt += s_red[s * 8 + w][1]; }
        float pprod = s_psim[s * H + 0] * s_psim[s * H + 1] * s_psim[s * H + 2];
        s_tot[s] = -__logf(pprod + EPSF) + sum / (cnt + EPSF);
    }
    __syncthreads();
    if (tid == 0)
        g_partial[blockIdx.x] = s_tot[0] + s_tot[1];

    // ================= Final: last block reduces 128 partials =================
    if (tid == 0) {
        __threadfence();
        s_amLast = (atomicAdd(&g_ticket, 1u) == NBLK - 1);
    }
    __syncthreads();
    if (s_amLast && warp == 0) {
        volatile float* gp = g_partial;
        float v = gp[lane] + gp[lane + 32] + gp[lane + 64] + gp[lane + 96];
        v = warp_sum32(v);
        if (lane == 0) {
            out[0] = v * (1.0f / (2.0f * (float)B));
            g_ticket = 0;
        }
    }
}

extern "C" void kernel_launch(void* const* d_in, const int* in_sizes, int n_in,
                              void* d_out, int out_size)
{
    const float* se   = (const float*)d_in[0];
    const float* c0   = (const float*)d_in[1];
    const float* c1   = (const float*)d_in[2];
    const float* c2   = (const float*)d_in[3];
    const int*   i2c0 = (const int*)d_in[4];
    const int*   i2c1 = (const int*)d_in[5];
    const int*   i2c2 = (const int*)d_in[6];
    const int*   idx  = (const int*)d_in[7];
    const int*   neg  = (const int*)d_in[8];
    float*       out  = (float*)d_out;

    hirl_fused<<<NBLK, NTHR>>>(se, c0, c1, c2, i2c0, i2c1, i2c2, idx, neg, out);
}